// round 13
// baseline (speedup 1.0000x reference)
#include <cuda_runtime.h>

// Problem constants
#define BB   1024
#define TT   512
#define II   100
#define HH   150
#define HP   160    // padded hidden (mult of 32)
#define OO   3

// Fused kernel geometry: 8-way chunk split x 2 j's per thread, 640 threads
#define NKC  8
#define KC   19     // W_hh k-chunk: 8*19 = 152 >= 150
#define IC   13     // W_ih i-chunk: 8*13 = 104 >= 100
#define HSK  152    // padded k extent of hs
#define HROW 8      // hs row stride (row 7 = pad)
#define ICP  104    // padded input extent
#define XR   12     // xstage row stride (48B: float4-aligned, 4-way STS conflict)
#define RB   7      // batch rows per CTA (147 CTAs)

// Output tuple layout: out, hidden, logits
#define HID_OFF  ((size_t)BB * TT * OO)
#define LOG_OFF  (HID_OFF + (size_t)BB * TT * HH)

// ---------------------------------------------------------------------------
// Fused kernel: input projection + sequential RNN. 147 CTAs x 7 rows,
// 640 threads (20 warps, 5/5/5/5 SMSP balance).
// Thread = (jp = tid%80, kc = tid/80 in [0,8)): two j's {jp, jp+80}.
//   W_hh[{jp,j1}][19kc..+18] (38 regs) + W_ih[{jp,j1}][13kc..+12] (26 regs)
// Per step the accumulators gather BOTH the W_hh(h) and W_ih(x) partials;
// cross-kc psum reduction (2 barriers/step) yields h(t+1) directly.
// x(t+1) staged transposed in smem, double-buffered, LDG issued at loop top.
// No g_xw scratch, no separate xw kernel (-493us, -335MB DRAM round trip).
// Reg budget ~95 < 102 cap at 640 thr -> no spill (R10's failure mode).
// ---------------------------------------------------------------------------
__global__ void __launch_bounds__(640, 1) rnn_fused_kernel(
        const float* __restrict__ x,
        const float* __restrict__ h0,
        const float* __restrict__ W_ih,
        const float* __restrict__ W_hh,
        float* __restrict__ out) {
    __shared__ __align__(16) float hs[2][HSK * HROW];    // [buf][k][row]
    __shared__ __align__(16) float xstage[2][ICP * XR];  // [buf][i][row]
    __shared__ float psum[NKC][RB * HP];                 // [kc][r*HP+j]

    const int tid = threadIdx.x;
    const int jp  = tid % 80;        // j pair: {jp, jp+80}
    const int kc  = tid / 80;        // [0,8)
    const int j1  = jp + 80;
    const bool j1v = (j1 < HH);      // jp < 70
    const int b0  = blockIdx.x * RB;
    const int nrows = (BB - b0 < RB) ? (BB - b0) : RB;

    // --- one-time: W_hh chunk into registers (zero-pad k >= 150) ---
    float w0[KC], w1[KC];
#pragma unroll
    for (int i = 0; i < KC; i++) {
        const int k = KC * kc + i;
        w0[i] = (k < HH) ? W_hh[jp * HH + k] : 0.f;
        w1[i] = (k < HH && j1v) ? W_hh[j1 * HH + k] : 0.f;
    }
    // --- one-time: W_ih chunk into registers (zero-pad i >= 100) ---
    float u0[IC], u1[IC];
#pragma unroll
    for (int i = 0; i < IC; i++) {
        const int gi = IC * kc + i;
        u0[i] = (gi < II) ? W_ih[jp * II + gi] : 0.f;
        u1[i] = (gi < II && j1v) ? W_ih[j1 * II + gi] : 0.f;
    }

    // --- init smem: zero hs + xstage (covers pads), fill h0 + x(0) ---
    for (int idx = tid; idx < 2 * HSK * HROW; idx += 640) ((float*)hs)[idx] = 0.f;
    for (int idx = tid; idx < 2 * ICP * XR; idx += 640) ((float*)xstage)[idx] = 0.f;
    __syncthreads();
    for (int idx = tid; idx < HH * nrows; idx += 640) {
        const int k = idx / nrows, r = idx - k * nrows;
        hs[0][k * HROW + r] = h0[(b0 + r) * HH + k];
    }
    // staging indices (fixed for the whole kernel)
    const int idx0 = tid, idx1 = tid + 640;
    const int s0r = idx0 / II, s0i = idx0 - s0r * II;
    const int s1r = idx1 / II, s1i = idx1 - s1r * II;
    const bool st0 = (idx0 < RB * II);
    const bool st1 = (idx1 < RB * II);
    if (st0 && s0r < nrows)
        xstage[0][s0i * XR + s0r] = x[((size_t)(b0 + s0r) * TT + 0) * II + s0i];
    if (st1 && s1r < nrows)
        xstage[0][s1i * XR + s1r] = x[((size_t)(b0 + s1r) * TT + 0) * II + s1i];
    __syncthreads();

    // ownership: kc < 7 owns row kc
    const int r_red = (kc < RB) ? kc : 0;
    const bool own  = (kc < RB) && (r_red < nrows);

    float* hid_out = out + HID_OFF;
    int cur = 0;

    for (int t = 0; t < TT; t++) {
        // --- issue LDG for x(t+1) early (latency hidden by FMA phase) ---
        float xld0 = 0.f, xld1 = 0.f;
        if (t + 1 < TT) {
            if (st0 && s0r < nrows)
                xld0 = x[((size_t)(b0 + s0r) * TT + (t + 1)) * II + s0i];
            if (st1 && s1r < nrows)
                xld1 = x[((size_t)(b0 + s1r) * TT + (t + 1)) * II + s1i];
        }

        float a0 = 0.f, a1 = 0.f, a2 = 0.f, a3 = 0.f, a4 = 0.f, a5 = 0.f, a6 = 0.f;
        float c0 = 0.f, c1 = 0.f, c2 = 0.f, c3 = 0.f, c4 = 0.f, c5 = 0.f, c6 = 0.f;

        // --- W_hh partial: 2 j's x 7 rows x 19 k; h broadcast from smem ---
        const float* hc = &hs[cur][(KC * kc) * HROW];
#pragma unroll
        for (int i = 0; i < KC; i++) {
            const float4 va = *(const float4*)(hc + i * HROW);       // rows 0-3
            const float4 vb = *(const float4*)(hc + i * HROW + 4);   // rows 4-6
            a0 = fmaf(w0[i], va.x, a0);  c0 = fmaf(w1[i], va.x, c0);
            a1 = fmaf(w0[i], va.y, a1);  c1 = fmaf(w1[i], va.y, c1);
            a2 = fmaf(w0[i], va.z, a2);  c2 = fmaf(w1[i], va.z, c2);
            a3 = fmaf(w0[i], va.w, a3);  c3 = fmaf(w1[i], va.w, c3);
            a4 = fmaf(w0[i], vb.x, a4);  c4 = fmaf(w1[i], vb.x, c4);
            a5 = fmaf(w0[i], vb.y, a5);  c5 = fmaf(w1[i], vb.y, c5);
            a6 = fmaf(w0[i], vb.z, a6);  c6 = fmaf(w1[i], vb.z, c6);
        }

        // --- W_ih partial: same accumulators; x(t) broadcast from smem ---
        const float* xc = &xstage[t & 1][(IC * kc) * XR];
#pragma unroll
        for (int i = 0; i < IC; i++) {
            const float4 va = *(const float4*)(xc + i * XR);         // rows 0-3
            const float4 vb = *(const float4*)(xc + i * XR + 4);     // rows 4-6
            a0 = fmaf(u0[i], va.x, a0);  c0 = fmaf(u1[i], va.x, c0);
            a1 = fmaf(u0[i], va.y, a1);  c1 = fmaf(u1[i], va.y, c1);
            a2 = fmaf(u0[i], va.z, a2);  c2 = fmaf(u1[i], va.z, c2);
            a3 = fmaf(u0[i], va.w, a3);  c3 = fmaf(u1[i], va.w, c3);
            a4 = fmaf(u0[i], vb.x, a4);  c4 = fmaf(u1[i], vb.x, c4);
            a5 = fmaf(u0[i], vb.y, a5);  c5 = fmaf(u1[i], vb.y, c5);
            a6 = fmaf(u0[i], vb.z, a6);  c6 = fmaf(u1[i], vb.z, c6);
        }

        // --- store x(t+1) into the other buffer (read/write bufs disjoint) ---
        if (t + 1 < TT) {
            if (st0) xstage[(t + 1) & 1][s0i * XR + s0r] = xld0;
            if (st1) xstage[(t + 1) & 1][s1i * XR + s1r] = xld1;
        }

        // --- write partials (both j's) ---
        float* ps = psum[kc] + jp;
        ps[0 * HP] = a0; ps[1 * HP] = a1; ps[2 * HP] = a2; ps[3 * HP] = a3;
        ps[4 * HP] = a4; ps[5 * HP] = a5; ps[6 * HP] = a6;
        float* ps1 = ps + 80;
        ps1[0 * HP] = c0; ps1[1 * HP] = c1; ps1[2 * HP] = c2; ps1[3 * HP] = c3;
        ps1[4 * HP] = c4; ps1[5 * HP] = c5; ps1[6 * HP] = c6;
        __syncthreads();

        // --- reduce owned row across 8 chunk partials, relu ---
        if (kc < RB) {
            float s00 = psum[0][r_red * HP + jp] + psum[1][r_red * HP + jp]
                      + psum[2][r_red * HP + jp] + psum[3][r_red * HP + jp]
                      + psum[4][r_red * HP + jp] + psum[5][r_red * HP + jp]
                      + psum[6][r_red * HP + jp] + psum[7][r_red * HP + jp];
            float s01 = psum[0][r_red * HP + j1] + psum[1][r_red * HP + j1]
                      + psum[2][r_red * HP + j1] + psum[3][r_red * HP + j1]
                      + psum[4][r_red * HP + j1] + psum[5][r_red * HP + j1]
                      + psum[6][r_red * HP + j1] + psum[7][r_red * HP + j1];
            s00 = fmaxf(s00, 0.f);
            s01 = fmaxf(s01, 0.f);

            // write next h state (transposed) + hidden output
            float* hn = hs[cur ^ 1];
            hn[jp * HROW + r_red] = s00;
            if (j1v) hn[j1 * HROW + r_red] = s01;
            if (own) {
                hid_out[((size_t)(b0 + r_red) * TT + t) * HH + jp] = s00;
                if (j1v) hid_out[((size_t)(b0 + r_red) * TT + t) * HH + j1] = s01;
            }
        }

        __syncthreads();
        cur ^= 1;
    }
}

// ---------------------------------------------------------------------------
// Kernel 2: logits = hidden @ W_fc^T; out = one_hot(argmax(logits+g)).
// Each warp processes 4 bt rows; all 20 hidden loads prefetched first.
// ---------------------------------------------------------------------------
__global__ void __launch_bounds__(256) post_kernel(const float* __restrict__ g,
                                                   const float* __restrict__ W_fc,
                                                   float* __restrict__ out) {
    __shared__ float wfc[OO * HP];
    const int tid = threadIdx.x;
    for (int i = tid; i < OO * HP; i += 256) {
        const int o = i / HP, k = i - o * HP;
        wfc[i] = (k < HH) ? W_fc[o * HH + k] : 0.f;
    }
    __syncthreads();

    const int warp = tid >> 5, lane = tid & 31;
    const size_t bt0 = ((size_t)blockIdx.x * 8 + warp) * 4;
    const float* hid = out + HID_OFF;

    float hv[4][5];
#pragma unroll
    for (int u = 0; u < 4; u++) {
        const float* hrow = hid + (bt0 + u) * HH;
#pragma unroll
        for (int m = 0; m < 5; m++) {
            const int k = lane + 32 * m;
            hv[u][m] = (k < HH) ? hrow[k] : 0.f;
        }
    }

#pragma unroll
    for (int u = 0; u < 4; u++) {
        const size_t bt = bt0 + u;
        float p[OO];
#pragma unroll
        for (int o = 0; o < OO; o++) {
            float s = 0.f;
#pragma unroll
            for (int m = 0; m < 5; m++)
                s = fmaf(hv[u][m], wfc[o * HP + lane + 32 * m], s);
#pragma unroll
            for (int off = 16; off > 0; off >>= 1)
                s += __shfl_xor_sync(0xffffffffu, s, off);
            p[o] = s;
        }
        if (lane == 0) {
            const float z0 = p[0] + g[bt * OO + 0];
            const float z1 = p[1] + g[bt * OO + 1];
            const float z2 = p[2] + g[bt * OO + 2];
            int idx = 0; float best = z0;
            if (z1 > best) { best = z1; idx = 1; }
            if (z2 > best) { best = z2; idx = 2; }
            float* op = out + bt * OO;
            op[0] = (idx == 0) ? 1.f : 0.f;
            op[1] = (idx == 1) ? 1.f : 0.f;
            op[2] = (idx == 2) ? 1.f : 0.f;
            float* lp = out + LOG_OFF + bt * OO;
            lp[0] = p[0]; lp[1] = p[1]; lp[2] = p[2];
        }
    }
}

// ---------------------------------------------------------------------------
extern "C" void kernel_launch(void* const* d_in, const int* in_sizes, int n_in,
                              void* d_out, int out_size) {
    const float* x    = (const float*)d_in[0];
    const float* h0   = (const float*)d_in[1];
    const float* g    = (const float*)d_in[2];
    const float* W_ih = (const float*)d_in[3];
    const float* W_hh = (const float*)d_in[4];
    const float* W_fc = (const float*)d_in[5];
    float* out = (float*)d_out;

    rnn_fused_kernel<<<(BB + RB - 1) / RB, 640>>>(x, h0, W_ih, W_hh, out);  // 147 CTAs
    post_kernel<<<(BB * TT) / 32, 256>>>(g, W_fc, out);                     // 16384 blocks
}

// round 15
// speedup vs baseline: 1.3365x; 1.3365x over previous
#include <cuda_runtime.h>

// Problem constants
#define BB   1024
#define TT   512
#define II   100
#define IIP  104    // x smem row stride (floats)
#define KPAD 108    // Wih2 row stride: 108 mod 32 = 12 -> conflict-free LDS.128
#define HH   150
#define HP   160    // padded hidden (mult of 32)
#define OO   3
#define XT   128    // xw rows per tile (4096 tiles)

// rnn kernel geometry: 8-way k split x 2 j's per thread, 640 threads
#define NKC  8
#define KC   19     // 8*19 = 152 >= 150
#define HSK  152    // padded k extent of hs
#define HROW 8      // hs row stride (row 7 = pad)
#define RB   7      // batch rows per rnn CTA (147 CTAs)

// Output tuple layout: out, hidden, logits
#define HID_OFF  ((size_t)BB * TT * OO)
#define LOG_OFF  (HID_OFF + (size_t)BB * TT * HH)

// Scratch: input projection xw[bt][HP] (~335 MB)
__device__ float g_xw[(size_t)BB * TT * HP];

__device__ __forceinline__ unsigned smem_u32(const void* p) {
    return (unsigned)__cvta_generic_to_shared(p);
}

// ---------------------------------------------------------------------------
// Kernel 1: xw[bt][j] = sum_i x[bt][i] * W_ih[j][i].
// 512 threads = (jq = tid&31, rgrp = tid>>5 in [0,16)): 5 j's (jq+32m) x
// 8 rows per thread. Weights held row-major in smem (Wih2[j][KPAD]) and
// loaded as LDS.128 (4 k's per instr, conflict-free via KPAD=108).
// Per kq per warp: 5 weight LDS.128 + 8 broadcast x LDS.128 = 173 issue
// slots per 160 FMA -> runs at the FMA-issue floor. XT=128 tiles,
// cp.async double-buffered, grid=148 persistent (1 CTA/SM, 176KB smem).
// ---------------------------------------------------------------------------
__global__ void __launch_bounds__(512, 1) xw_kernel(const float* __restrict__ x,
                                                    const float* __restrict__ W_ih) {
    extern __shared__ float sm[];
    float* Wih2 = sm;                    // [160][KPAD]  (69120 B)
    float* xs0  = sm + HP * KPAD;        // [XT][IIP]
    float* xs1  = xs0 + XT * IIP;        // [XT][IIP]
    const int tid = threadIdx.x;

    // fill Wih2 row-major, zero-padded (j >= 150 or k >= 100 -> 0)
    for (int idx = tid; idx < HP * KPAD; idx += 512) {
        const int j = idx / KPAD, k = idx - j * KPAD;
        Wih2[idx] = (j < HH && k < II) ? W_ih[j * II + k] : 0.f;
    }

    const int jq   = tid & 31;           // j = jq + 32m, m < 5
    const int rgrp = tid >> 5;           // rows rgrp*8 .. rgrp*8+7
    const int nTiles = (BB * TT) / XT;   // 4096

    // async-stage: 128 rows x 25 16B chunks = 3200 copies
    auto stage = [&](float* dst, int tile) {
        const int bt0 = tile * XT;
#pragma unroll
        for (int s = 0; s < 7; s++) {
            const int c = tid + s * 512;
            if (c < XT * 25) {
                const int r = c / 25, k = c - r * 25;
                const float* src = x + (size_t)(bt0 + r) * II + k * 4;
                const unsigned d = smem_u32(dst + r * IIP + k * 4);
                asm volatile("cp.async.ca.shared.global [%0], [%1], 16;"
                             :: "r"(d), "l"(src));
            }
        }
    };

    stage(xs0, blockIdx.x);
    asm volatile("cp.async.commit_group;");
    asm volatile("cp.async.wait_group 0;");
    __syncthreads();

    int buf = 0;
    for (int tile = blockIdx.x; tile < nTiles; tile += gridDim.x) {
        const int next = tile + gridDim.x;
        float* cur = buf ? xs1 : xs0;
        float* oth = buf ? xs0 : xs1;
        if (next < nTiles) stage(oth, next);
        asm volatile("cp.async.commit_group;");

        const int bt0 = tile * XT;
        float acc[5][8];
#pragma unroll
        for (int m = 0; m < 5; m++)
#pragma unroll
            for (int r = 0; r < 8; r++) acc[m][r] = 0.f;

        const float* xrow = cur + rgrp * 8 * IIP;
        const float* wbase = Wih2 + jq * KPAD;
#pragma unroll 5
        for (int kq = 0; kq < II / 4; kq++) {
            float4 w[5];
#pragma unroll
            for (int m = 0; m < 5; m++)
                w[m] = *(const float4*)(wbase + (32 * m) * KPAD + 4 * kq);
#pragma unroll
            for (int r = 0; r < 8; r++) {
                const float4 xv = *(const float4*)(xrow + r * IIP + 4 * kq);  // broadcast
#pragma unroll
                for (int m = 0; m < 5; m++) {
                    acc[m][r] = fmaf(w[m].x, xv.x, acc[m][r]);
                    acc[m][r] = fmaf(w[m].y, xv.y, acc[m][r]);
                    acc[m][r] = fmaf(w[m].z, xv.z, acc[m][r]);
                    acc[m][r] = fmaf(w[m].w, xv.w, acc[m][r]);
                }
            }
        }

#pragma unroll
        for (int m = 0; m < 5; m++)
#pragma unroll
            for (int r = 0; r < 8; r++)
                g_xw[(size_t)(bt0 + rgrp * 8 + r) * HP + jq + 32 * m] = acc[m][r];

        asm volatile("cp.async.wait_group 0;");
        __syncthreads();
        buf ^= 1;
    }
}

// ---------------------------------------------------------------------------
// Kernel 2: sequential RNN (R12 verbatim — measured ~775us).
// 147 CTAs x 7 rows, 640 threads (20 warps, 5/5/5/5 SMSP balance).
// Thread = (jp = tid%80, kc = tid/80 in [0,8)): two j's {jp, jp+80},
// W_hh[{jp,j1}][19kc..+18] in registers. Warp-uniform broadcast LDS.
// Cross-kc reduction via smem psum, 2 barriers/step.
// ---------------------------------------------------------------------------
__global__ void __launch_bounds__(640, 1) rnn_kernel(const float* __restrict__ h0,
                                                     const float* __restrict__ W_hh,
                                                     float* __restrict__ out) {
    __shared__ __align__(16) float hs[2][HSK * HROW];  // [buf][k][row]
    __shared__ float psum[NKC][RB * HP];                // [kc][r*HP+j]

    const int tid = threadIdx.x;
    const int jp  = tid % 80;        // j pair: {jp, jp+80}
    const int kc  = tid / 80;        // [0,8)
    const int j1  = jp + 80;
    const bool j1v = (j1 < HH);      // jp < 70
    const int b0  = blockIdx.x * RB;
    const int nrows = (BB - b0 < RB) ? (BB - b0) : RB;

    float w0[KC], w1[KC];
#pragma unroll
    for (int i = 0; i < KC; i++) {
        const int k = KC * kc + i;
        w0[i] = (k < HH) ? W_hh[jp * HH + k] : 0.f;
        w1[i] = (k < HH && j1v) ? W_hh[j1 * HH + k] : 0.f;
    }

    for (int idx = tid; idx < 2 * HSK * HROW; idx += 640) ((float*)hs)[idx] = 0.f;
    __syncthreads();
    for (int idx = tid; idx < HH * nrows; idx += 640) {
        const int k = idx / nrows, r = idx - k * nrows;
        hs[0][k * HROW + r] = h0[(b0 + r) * HH + k];
    }
    __syncthreads();

    const int r_red = (kc < RB) ? kc : 0;
    const bool own  = (kc < RB) && (r_red < nrows);
    const int r_ld  = own ? r_red : 0;              // CLAMPED prefetch row
    const float* px0 = g_xw + ((size_t)(b0 + r_ld) * TT) * HP + jp;
    float xw00 = px0[0], xw01 = px0[80];

    float* hid_out = out + HID_OFF;
    int cur = 0;

    for (int t = 0; t < TT; t++) {
        float n00 = 0.f, n01 = 0.f;
        if (t + 1 < TT) { n00 = px0[HP]; n01 = px0[HP + 80]; }

        const float* hc = &hs[cur][(KC * kc) * HROW];
        float a0 = 0.f, a1 = 0.f, a2 = 0.f, a3 = 0.f, a4 = 0.f, a5 = 0.f, a6 = 0.f;
        float c0 = 0.f, c1 = 0.f, c2 = 0.f, c3 = 0.f, c4 = 0.f, c5 = 0.f, c6 = 0.f;
#pragma unroll
        for (int i = 0; i < KC; i++) {
            const float4 va = *(const float4*)(hc + i * HROW);       // rows 0-3
            const float4 vb = *(const float4*)(hc + i * HROW + 4);   // rows 4-6
            a0 = fmaf(w0[i], va.x, a0);  c0 = fmaf(w1[i], va.x, c0);
            a1 = fmaf(w0[i], va.y, a1);  c1 = fmaf(w1[i], va.y, c1);
            a2 = fmaf(w0[i], va.z, a2);  c2 = fmaf(w1[i], va.z, c2);
            a3 = fmaf(w0[i], va.w, a3);  c3 = fmaf(w1[i], va.w, c3);
            a4 = fmaf(w0[i], vb.x, a4);  c4 = fmaf(w1[i], vb.x, c4);
            a5 = fmaf(w0[i], vb.y, a5);  c5 = fmaf(w1[i], vb.y, c5);
            a6 = fmaf(w0[i], vb.z, a6);  c6 = fmaf(w1[i], vb.z, c6);
        }

        float* ps = psum[kc] + jp;
        ps[0 * HP] = a0; ps[1 * HP] = a1; ps[2 * HP] = a2; ps[3 * HP] = a3;
        ps[4 * HP] = a4; ps[5 * HP] = a5; ps[6 * HP] = a6;
        float* ps1 = ps + 80;
        ps1[0 * HP] = c0; ps1[1 * HP] = c1; ps1[2 * HP] = c2; ps1[3 * HP] = c3;
        ps1[4 * HP] = c4; ps1[5 * HP] = c5; ps1[6 * HP] = c6;
        __syncthreads();

        if (kc < RB) {
            float s00 = psum[0][r_red * HP + jp] + psum[1][r_red * HP + jp]
                      + psum[2][r_red * HP + jp] + psum[3][r_red * HP + jp]
                      + psum[4][r_red * HP + jp] + psum[5][r_red * HP + jp]
                      + psum[6][r_red * HP + jp] + psum[7][r_red * HP + jp] + xw00;
            float s01 = psum[0][r_red * HP + j1] + psum[1][r_red * HP + j1]
                      + psum[2][r_red * HP + j1] + psum[3][r_red * HP + j1]
                      + psum[4][r_red * HP + j1] + psum[5][r_red * HP + j1]
                      + psum[6][r_red * HP + j1] + psum[7][r_red * HP + j1] + xw01;
            s00 = fmaxf(s00, 0.f);
            s01 = fmaxf(s01, 0.f);

            float* hn = hs[cur ^ 1];
            hn[jp * HROW + r_red] = s00;
            if (j1v) hn[j1 * HROW + r_red] = s01;
            if (own) {
                hid_out[((size_t)(b0 + r_red) * TT + t) * HH + jp] = s00;
                if (j1v) hid_out[((size_t)(b0 + r_red) * TT + t) * HH + j1] = s01;
            }
        }

        xw00 = n00; xw01 = n01;
        px0 += HP;
        __syncthreads();
        cur ^= 1;
    }
}

// ---------------------------------------------------------------------------
// Kernel 3: logits = hidden @ W_fc^T; out = one_hot(argmax(logits+g)).
// 4 bt rows per warp, all 20 hidden loads prefetched (measured 86us).
// ---------------------------------------------------------------------------
__global__ void __launch_bounds__(256) post_kernel(const float* __restrict__ g,
                                                   const float* __restrict__ W_fc,
                                                   float* __restrict__ out) {
    __shared__ float wfc[OO * HP];
    const int tid = threadIdx.x;
    for (int i = tid; i < OO * HP; i += 256) {
        const int o = i / HP, k = i - o * HP;
        wfc[i] = (k < HH) ? W_fc[o * HH + k] : 0.f;
    }
    __syncthreads();

    const int warp = tid >> 5, lane = tid & 31;
    const size_t bt0 = ((size_t)blockIdx.x * 8 + warp) * 4;
    const float* hid = out + HID_OFF;

    float hv[4][5];
#pragma unroll
    for (int u = 0; u < 4; u++) {
        const float* hrow = hid + (bt0 + u) * HH;
#pragma unroll
        for (int m = 0; m < 5; m++) {
            const int k = lane + 32 * m;
            hv[u][m] = (k < HH) ? hrow[k] : 0.f;
        }
    }

#pragma unroll
    for (int u = 0; u < 4; u++) {
        const size_t bt = bt0 + u;
        float p[OO];
#pragma unroll
        for (int o = 0; o < OO; o++) {
            float s = 0.f;
#pragma unroll
            for (int m = 0; m < 5; m++)
                s = fmaf(hv[u][m], wfc[o * HP + lane + 32 * m], s);
#pragma unroll
            for (int off = 16; off > 0; off >>= 1)
                s += __shfl_xor_sync(0xffffffffu, s, off);
            p[o] = s;
        }
        if (lane == 0) {
            const float z0 = p[0] + g[bt * OO + 0];
            const float z1 = p[1] + g[bt * OO + 1];
            const float z2 = p[2] + g[bt * OO + 2];
            int idx = 0; float best = z0;
            if (z1 > best) { best = z1; idx = 1; }
            if (z2 > best) { best = z2; idx = 2; }
            float* op = out + bt * OO;
            op[0] = (idx == 0) ? 1.f : 0.f;
            op[1] = (idx == 1) ? 1.f : 0.f;
            op[2] = (idx == 2) ? 1.f : 0.f;
            float* lp = out + LOG_OFF + bt * OO;
            lp[0] = p[0]; lp[1] = p[1]; lp[2] = p[2];
        }
    }
}

// ---------------------------------------------------------------------------
extern "C" void kernel_launch(void* const* d_in, const int* in_sizes, int n_in,
                              void* d_out, int out_size) {
    const float* x    = (const float*)d_in[0];
    const float* h0   = (const float*)d_in[1];
    const float* g    = (const float*)d_in[2];
    const float* W_ih = (const float*)d_in[3];
    const float* W_hh = (const float*)d_in[4];
    const float* W_fc = (const float*)d_in[5];
    float* out = (float*)d_out;

    const int xw_smem = (HP * KPAD + 2 * XT * IIP) * (int)sizeof(float);   // ~176 KB
    cudaFuncSetAttribute(xw_kernel, cudaFuncAttributeMaxDynamicSharedMemorySize, xw_smem);

    xw_kernel<<<148, 512, xw_smem>>>(x, W_ih);                // persistent, 1 CTA/SM
    rnn_kernel<<<(BB + RB - 1) / RB, 640>>>(h0, W_hh, out);   // 147 CTAs
    post_kernel<<<(BB * TT) / 32, 256>>>(g, W_fc, out);       // 16384 blocks
}